// round 13
// baseline (speedup 1.0000x reference)
#include <cuda_runtime.h>
#include <stdint.h>

// Sort_Latent_Layer: z (B, 1, 8192) fp32. Per row: 512 packets x 16 floats,
// stable-sort packets by packet[0] ascending, gather, write back.
//
// R12: SCATTER formulation -- floor traffic (256 MB), no key read.
//   CTA per row, 288 threads = 8 data warps + 1 sort warp.
//     data warps: coalesced __ldcs of the whole row into registers
//                 (keys are packet[0] = .x of every 4th float4 -> smem)
//     sort warp : register/shfl bitonic on 512 keys (bit-exact since R4),
//                 writes inverse perm sinv[src]=dst to smem
//     data warps: scatter-write, each quad stores its packet as one
//                 contiguous 64B chunk at out[dst] (__stcs, full sectors)
//   Reads 128 MB coalesced + writes 128 MB full-sector random = floor.

#define NPK 512
#define V   16
#define THREADS 288            // 9 warps

__device__ __forceinline__ void ce(unsigned long long &x, unsigned long long &y, bool up)
{
    bool sw = (x > y) == up;          // items are distinct (idx in low bits)
    unsigned long long a = sw ? y : x;
    unsigned long long b = sw ? x : y;
    x = a; y = b;
}

__global__ void __launch_bounds__(THREADS, 3)
sort_latent_scatter(const float* __restrict__ z, float* __restrict__ out)
{
    __shared__ uint32_t skey[NPK];     // monotone-mapped keys
    __shared__ uint16_t sinv[NPK];     // sinv[src packet] = dst rank

    const int t    = threadIdx.x;
    const int w    = t >> 5;
    const int lane = t & 31;
    const long long row = blockIdx.x;

    const float4* __restrict__ in4  = (const float4*)(z   + row * 8192);
    float4* __restrict__       out4 = (float4*)(out + row * 8192);

    // ---- phase 1: data warps load row coalesced, publish keys ----
    float4 d[8];
    if (w < 8) {
        #pragma unroll
        for (int u = 0; u < 8; ++u)
            d[u] = __ldcs(&in4[u * 256 + t]);          // fully coalesced

        #pragma unroll
        for (int u = 0; u < 8; ++u) {
            if ((t & 3) == 0) {                        // holds packet[0]
                int p = (u * 256 + t) >> 2;            // packet index
                uint32_t kb = __float_as_uint(d[u].x);
                kb = (kb & 0x80000000u) ? ~kb : (kb | 0x80000000u);  // monotone
                skey[p] = kb;
            }
        }
    }
    __syncthreads();

    // ---- phase 2: sort warp (warp 8) ranks all 512 packets ----
    if (w == 8) {
        unsigned long long it[V];
        #pragma unroll
        for (int v = 0; v < V; ++v) {
            int i = lane * V + v;                      // blocked item layout
            it[v] = ((unsigned long long)skey[i] << 32) | (unsigned)i;
        }

        // bitonic sort, 512 items: register-local (j<16) + shfl (j>=16)
        #pragma unroll
        for (int k = 2; k <= V; k <<= 1) {
            #pragma unroll
            for (int j = k >> 1; j >= 1; j >>= 1) {
                #pragma unroll
                for (int v = 0; v < V; ++v) {
                    if ((v & j) == 0) {
                        int i = lane * V + v;
                        bool up = ((i & k) == 0);
                        ce(it[v], it[v | j], up);
                    }
                }
            }
        }
        #pragma unroll
        for (int k = 32; k <= 512; k <<= 1) {
            const bool up = ((lane & (k >> 4)) == 0);
            #pragma unroll
            for (int j = k >> 1; j >= V; j >>= 1) {
                const int  dl      = j >> 4;
                const bool keepmin = (((lane & dl) == 0) == up);
                #pragma unroll
                for (int v = 0; v < V; ++v) {
                    unsigned long long other = __shfl_xor_sync(0xFFFFFFFFu, it[v], dl);
                    if ((other < it[v]) == keepmin) it[v] = other;
                }
            }
            #pragma unroll
            for (int j = V >> 1; j >= 1; j >>= 1) {
                #pragma unroll
                for (int v = 0; v < V; ++v)
                    if ((v & j) == 0) ce(it[v], it[v | j], up);
            }
        }

        // sorted position d = lane*16+v holds source packet (it & 511)
        #pragma unroll
        for (int v = 0; v < V; ++v)
            sinv[(int)(it[v] & 0x1FFu)] = (uint16_t)(lane * V + v);
    }
    __syncthreads();

    // ---- phase 3: scatter (quad writes one contiguous 64B packet chunk) ----
    if (w < 8) {
        #pragma unroll
        for (int u = 0; u < 8; ++u) {
            int f   = u * 256 + t;
            int p   = f >> 2;                          // source packet
            int dst = sinv[p];                         // quad-broadcast LDS
            __stcs(&out4[dst * 4 + (f & 3)], d[u]);    // full-sector 64B chunk
        }
    }
}

extern "C" void kernel_launch(void* const* d_in, const int* in_sizes, int n_in,
                              void* d_out, int out_size)
{
    const float* z = (const float*)d_in[0];
    float* out     = (float*)d_out;
    const int D = 8192;                  // 512 packets * 16 floats
    int B = in_sizes[0] / D;             // 4096

    sort_latent_scatter<<<B, THREADS>>>(z, out);
}

// round 14
// speedup vs baseline: 1.4420x; 1.4420x over previous
#include <cuda_runtime.h>
#include <stdint.h>

// Sort_Latent_Layer: z (B, 1, 8192) fp32. Per row: 512 packets x 16 floats,
// stable-sort packets by packet[0] ascending, gather, write back.
//
// R13: floor-traffic SCATTER (R12-validated, ~225 MB) + 5-deep smem pipeline
// so the sort is off the critical path.
//   1 CTA/SM (grid 148), 448 threads = 14 warps:
//     warp 13      : TMA producer  -- cp.async.bulk row -> slot (5 ahead)
//     warps 8..12  : sort warp s owns slot s: full-wait -> keys from smem
//                    (cyclic LDS -> padded-tile transpose -> blocked) ->
//                    register/shfl bitonic (bit-exact since R4) -> sinv -> perm
//     warps 0..7   : scatter: perm-wait -> LDS row linear -> __stcs 64B
//                    packet chunks at out[dst] -> free (slot reuse)
//   mbarriers per slot: full(1), perm(1), free(8).

#define NPK   512
#define V     16
#define SLOTS 5
#define SCAT_WARPS 8
#define SORT_W0    8
#define TMA_W      13
#define THREADS    448

#define ROW_BYTES  32768
#define TPAD       36
#define TILE_WORDS 576

#define OFF_DATA 0
#define OFF_SINV (SLOTS * ROW_BYTES)                    // 163840
#define OFF_TILE (OFF_SINV + SLOTS * NPK * 2)           // 168960
#define OFF_MBAR (OFF_TILE + SLOTS * TILE_WORDS * 4)    // 180480
#define SMEM_TOTAL (OFF_MBAR + 3 * SLOTS * 8 + 64)

__device__ __forceinline__ uint32_t smem_u32(const void* p)
{
    uint32_t a;
    asm("{ .reg .u64 t; cvta.to.shared.u64 t, %1; cvt.u32.u64 %0, t; }"
        : "=r"(a) : "l"(p));
    return a;
}

__device__ __forceinline__ void mbar_wait(uint32_t mbar, uint32_t parity)
{
    uint32_t done;
    asm volatile(
        "{\n\t.reg .pred p;\n\t"
        "mbarrier.try_wait.parity.acquire.cta.shared::cta.b64 p, [%1], %2;\n\t"
        "selp.b32 %0, 1, 0, p;\n\t}"
        : "=r"(done) : "r"(mbar), "r"(parity) : "memory");
    if (!done) {
        asm volatile(
            "{\n\t.reg .pred P1;\n\t"
            "W_%=:\n\t"
            "mbarrier.try_wait.parity.acquire.cta.shared::cta.b64 P1, [%0], %1, 0x989680;\n\t"
            "@P1 bra.uni D_%=;\n\t"
            "bra.uni W_%=;\n\t"
            "D_%=:\n\t}"
            :: "r"(mbar), "r"(parity) : "memory");
    }
}

__device__ __forceinline__ void ce(unsigned long long &x, unsigned long long &y, bool up)
{
    bool sw = (x > y) == up;          // items distinct (idx in low bits)
    unsigned long long a = sw ? y : x;
    unsigned long long b = sw ? x : y;
    x = a; y = b;
}

__global__ void __launch_bounds__(THREADS, 1)
sort_latent_pipe(const float* __restrict__ z, float* __restrict__ out, int B)
{
    extern __shared__ char smem[];

    const int tid   = threadIdx.x;
    const int w     = tid >> 5;
    const int lane  = tid & 31;
    const int base  = blockIdx.x;
    const int strd  = gridDim.x;
    const int cnt   = (B > base) ? (B - base + strd - 1) / strd : 0;

    const uint32_t mb0 = smem_u32(smem + OFF_MBAR);
    #define MB_FULL(s) (mb0 + (uint32_t)(s) * 8u)
    #define MB_PERM(s) (mb0 + (uint32_t)(SLOTS + (s)) * 8u)
    #define MB_FREE(s) (mb0 + (uint32_t)(2 * SLOTS + (s)) * 8u)

    if (tid == 0) {
        #pragma unroll
        for (int s = 0; s < SLOTS; ++s) {
            asm volatile("mbarrier.init.shared.b64 [%0], 1;"  :: "r"(MB_FULL(s)) : "memory");
            asm volatile("mbarrier.init.shared.b64 [%0], 1;"  :: "r"(MB_PERM(s)) : "memory");
            asm volatile("mbarrier.init.shared.b64 [%0], %1;" :: "r"(MB_FREE(s)), "r"(SCAT_WARPS) : "memory");
        }
        asm volatile("fence.proxy.async.shared::cta;" ::: "memory");
    }
    __syncthreads();
    if (cnt <= 0) return;

    // ---------------- TMA producer (warp 13, lane 0) ----------------
    if (w == TMA_W) {
        if (lane == 0) {
            #pragma unroll 1
            for (int i = 0; i < cnt; ++i) {
                int s     = i % SLOTS;
                int reuse = i / SLOTS;
                mbar_wait(MB_FREE(s), (uint32_t)((reuse & 1) ^ 1));   // reuse 0 passes
                const float* src = z + (long long)(base + i * strd) * 8192;
                uint32_t dst = smem_u32(smem + OFF_DATA + s * ROW_BYTES);
                asm volatile("mbarrier.arrive.expect_tx.shared.b64 _, [%0], %1;"
                             :: "r"(MB_FULL(s)), "r"(ROW_BYTES) : "memory");
                asm volatile(
                    "cp.async.bulk.shared::cluster.global.mbarrier::complete_tx::bytes "
                    "[%0], [%1], %2, [%3];"
                    :: "r"(dst), "l"(src), "r"(ROW_BYTES), "r"(MB_FULL(s))
                    : "memory");
            }
        }
        return;
    }

    // ---------------- sort warps (8..12): warp s owns slot s ----------------
    if (w >= SORT_W0) {
        const int s = w - SORT_W0;
        const float*    sd   = (const float*)(smem + OFF_DATA + s * ROW_BYTES);
        uint32_t*       tile = (uint32_t*)(smem + OFF_TILE + s * TILE_WORDS * 4);
        uint16_t*       sinv = (uint16_t*)(smem + OFF_SINV + s * NPK * 2);

        #pragma unroll 1
        for (int i = s; i < cnt; i += SLOTS) {
            int reuse = i / SLOTS;
            mbar_wait(MB_FULL(s), (uint32_t)(reuse & 1));

            // cyclic key read (16-way-conflict LDS, cheap) -> padded tile
            #pragma unroll
            for (int vs = 0; vs < V; ++vs) {
                uint32_t kb = __float_as_uint(sd[(vs * 32 + lane) * 16]);
                kb = (kb & 0x80000000u) ? ~kb : (kb | 0x80000000u);   // monotone
                tile[vs * TPAD + lane] = kb;
            }
            __syncwarp();

            // blocked read-back: it[v] = item lane*16+v (conflict-free LDS.128)
            unsigned long long it[V];
            {
                const uint32_t b2 = (uint32_t)(lane >> 1) * TPAD + (uint32_t)(lane & 1) * 16;
                #pragma unroll
                for (int t = 0; t < V / 4; ++t) {
                    uint4 kk = *reinterpret_cast<const uint4*>(tile + b2 + t * 4);
                    int i0 = lane * V + t * 4;
                    it[t*4+0] = ((unsigned long long)kk.x << 32) | (unsigned)(i0+0);
                    it[t*4+1] = ((unsigned long long)kk.y << 32) | (unsigned)(i0+1);
                    it[t*4+2] = ((unsigned long long)kk.z << 32) | (unsigned)(i0+2);
                    it[t*4+3] = ((unsigned long long)kk.w << 32) | (unsigned)(i0+3);
                }
            }

            // bitonic 512: register-local (j<16) + shfl (j>=16)  [bit-exact since R4]
            #pragma unroll
            for (int k = 2; k <= V; k <<= 1) {
                #pragma unroll
                for (int j = k >> 1; j >= 1; j >>= 1) {
                    #pragma unroll
                    for (int v = 0; v < V; ++v) {
                        if ((v & j) == 0) {
                            int ii = lane * V + v;
                            bool up = ((ii & k) == 0);
                            ce(it[v], it[v | j], up);
                        }
                    }
                }
            }
            #pragma unroll
            for (int k = 32; k <= 512; k <<= 1) {
                const bool up = ((lane & (k >> 4)) == 0);
                #pragma unroll
                for (int j = k >> 1; j >= V; j >>= 1) {
                    const int  dl      = j >> 4;
                    const bool keepmin = (((lane & dl) == 0) == up);
                    #pragma unroll
                    for (int v = 0; v < V; ++v) {
                        unsigned long long o = __shfl_xor_sync(0xFFFFFFFFu, it[v], dl);
                        if ((o < it[v]) == keepmin) it[v] = o;
                    }
                }
                #pragma unroll
                for (int j = V >> 1; j >= 1; j >>= 1) {
                    #pragma unroll
                    for (int v = 0; v < V; ++v)
                        if ((v & j) == 0) ce(it[v], it[v | j], up);
                }
            }

            // inverse perm: sinv[src] = dst rank
            #pragma unroll
            for (int v = 0; v < V; ++v)
                sinv[(int)(it[v] & 0x1FFu)] = (uint16_t)(lane * V + v);
            __syncwarp();
            if (lane == 0)
                asm volatile("mbarrier.arrive.shared.b64 _, [%0];" :: "r"(MB_PERM(s)) : "memory");
        }
        return;
    }

    // ---------------- scatter warps (0..7) ----------------
    {
        #pragma unroll 1
        for (int i = 0; i < cnt; ++i) {
            int s     = i % SLOTS;
            int reuse = i / SLOTS;
            mbar_wait(MB_PERM(s), (uint32_t)(reuse & 1));

            const float4*   sd4  = (const float4*)(smem + OFF_DATA + s * ROW_BYTES);
            const uint16_t* sinv = (const uint16_t*)(smem + OFF_SINV + s * NPK * 2);
            float4* out4 = (float4*)(out + (long long)(base + i * strd) * 8192);

            int    dst[8];
            float4 v4[8];
            #pragma unroll
            for (int u = 0; u < 8; ++u) {
                int f  = w * 256 + u * 32 + lane;
                dst[u] = sinv[f >> 2];                 // quad-broadcast LDS
                v4[u]  = sd4[f];                       // linear LDS.128
            }
            #pragma unroll
            for (int u = 0; u < 8; ++u) {
                int f = w * 256 + u * 32 + lane;
                __stcs(&out4[dst[u] * 4 + (f & 3)], v4[u]);  // full-sector 64B chunk
            }
            __syncwarp();
            if (lane == 0)
                asm volatile("mbarrier.arrive.shared.b64 _, [%0];" :: "r"(MB_FREE(s)) : "memory");
        }
    }
}

extern "C" void kernel_launch(void* const* d_in, const int* in_sizes, int n_in,
                              void* d_out, int out_size)
{
    const float* z = (const float*)d_in[0];
    float* out     = (float*)d_out;
    const int D = 8192;                  // 512 packets * 16 floats
    int B = in_sizes[0] / D;             // 4096

    static int inited = 0;
    if (!inited) {
        cudaFuncSetAttribute(sort_latent_pipe,
                             cudaFuncAttributeMaxDynamicSharedMemorySize,
                             SMEM_TOTAL);
        inited = 1;
    }
    int grid = B < 148 ? B : 148;        // 1 CTA per SM, rows cyclic
    sort_latent_pipe<<<grid, THREADS, SMEM_TOTAL>>>(z, out, B);
}

// round 15
// speedup vs baseline: 2.1450x; 1.4875x over previous
#include <cuda_runtime.h>
#include <stdint.h>

// Sort_Latent_Layer: z (B, 1, 8192) fp32. Per row: 512 packets x 16 floats,
// stable-sort packets by packet[0] ascending, gather, write back.
//
// R14: CTA-per-row scatter with TMA staging and a 4-warp cooperative bitonic.
//   - 128 threads (4 warps), ~37 KB smem -> 6 CTAs/SM, 24 warps/SM.
//   - TMA cp.async.bulk stages the 32KB row; keys come from smem (no extra
//     global key read -> traffic stays at the 256 MB floor, proven R12/R13).
//   - bitonic 512 split across 4 warps, V=4 items/lane:
//       j in {1,2}   register compare-exchange
//       j in {4..64} shfl_xor (dl = j/4)
//       j in {128,256} smem exchange + __syncthreads (3 stages total)
//     -> sort latency ~4x lower than 1-warp version; issue load spread
//        over all warps.
//   - scatter: linear LDS.128 + quad-contiguous 64B __stcs chunks at out[dst]
//     (full sectors; write volume exactly 128 MB).

#define THREADS 128
#define ROW_BYTES 32768

#define OFF_SORT 32768                    // u64 ssort[512]  (4 KB)
#define OFF_SINV (OFF_SORT + 4096)        // u16 sinv[512]   (1 KB)
#define OFF_MBAR (OFF_SINV + 1024)
#define SMEM_TOTAL (OFF_MBAR + 16)

__device__ __forceinline__ uint32_t smem_u32(const void* p)
{
    uint32_t a;
    asm("{ .reg .u64 t; cvta.to.shared.u64 t, %1; cvt.u32.u64 %0, t; }"
        : "=r"(a) : "l"(p));
    return a;
}

__device__ __forceinline__ void mbar_wait0(uint32_t mbar)
{
    uint32_t done;
    asm volatile(
        "{\n\t.reg .pred p;\n\t"
        "mbarrier.try_wait.parity.acquire.cta.shared::cta.b64 p, [%1], 0;\n\t"
        "selp.b32 %0, 1, 0, p;\n\t}"
        : "=r"(done) : "r"(mbar) : "memory");
    if (!done) {
        asm volatile(
            "{\n\t.reg .pred P1;\n\t"
            "W_%=:\n\t"
            "mbarrier.try_wait.parity.acquire.cta.shared::cta.b64 P1, [%0], 0, 0x989680;\n\t"
            "@P1 bra.uni D_%=;\n\t"
            "bra.uni W_%=;\n\t"
            "D_%=:\n\t}"
            :: "r"(mbar) : "memory");
    }
}

__device__ __forceinline__ void ce(unsigned long long &x, unsigned long long &y, bool up)
{
    bool sw = (x > y) == up;          // items distinct (idx in low bits)
    unsigned long long a = sw ? y : x;
    unsigned long long b = sw ? x : y;
    x = a; y = b;
}

// one shfl stage over the 4 register items, distance dl lanes, comparator bit j
__device__ __forceinline__ void shfl_stage(unsigned long long it[4],
                                           int lane, int j, bool up)
{
    const int  dl      = j >> 2;
    const bool keepmin = (((lane * 4) & j) == 0) == up;   // j>=4: (li&j) == (lane*4)&j
    #pragma unroll
    for (int v = 0; v < 4; ++v) {
        unsigned long long o = __shfl_xor_sync(0xFFFFFFFFu, it[v], dl);
        if ((o < it[v]) == keepmin) it[v] = o;
    }
}

__global__ void __launch_bounds__(THREADS)
sort_latent_r14(const float* __restrict__ z, float* __restrict__ out)
{
    extern __shared__ char smem[];
    float4*             sdata = (float4*)smem;
    unsigned long long* ssort = (unsigned long long*)(smem + OFF_SORT);
    uint16_t*           sinv  = (uint16_t*)(smem + OFF_SINV);
    const uint32_t      mbar  = smem_u32(smem + OFF_MBAR);

    const int t    = threadIdx.x;
    const int w    = t >> 5;
    const int lane = t & 31;
    const long long row = blockIdx.x;

    if (t == 0)
        asm volatile("mbarrier.init.shared.b64 [%0], 1;" :: "r"(mbar) : "memory");
    __syncthreads();
    if (t == 0) {
        asm volatile("mbarrier.arrive.expect_tx.shared.b64 _, [%0], %1;"
                     :: "r"(mbar), "r"(ROW_BYTES) : "memory");
        asm volatile(
            "cp.async.bulk.shared::cluster.global.mbarrier::complete_tx::bytes "
            "[%0], [%1], %2, [%3];"
            :: "r"(smem_u32(sdata)), "l"(z + row * 8192), "r"(ROW_BYTES), "r"(mbar)
            : "memory");
    }
    mbar_wait0(mbar);                  // all 128 threads; acquire

    // ---- build items: i = w*128 + lane*4 + v, key = smem word i*16 ----
    const float* sdf = (const float*)sdata;
    const int i0 = w * 128 + lane * 4;
    unsigned long long it[4];
    #pragma unroll
    for (int v = 0; v < 4; ++v) {
        uint32_t kb = __float_as_uint(sdf[(i0 + v) * 16]);
        kb = (kb & 0x80000000u) ? ~kb : (kb | 0x80000000u);   // monotone map
        it[v] = ((unsigned long long)kb << 32) | (unsigned)(i0 + v);
    }

    // ---- bitonic 512, 4-warp cooperative ----
    // k = 2: reg, direction from v
    ce(it[0], it[1], true);
    ce(it[2], it[3], false);

    // k = 4..64: intra-warp; up = ((lane*4) & k) == 0 (k>=4)
    #pragma unroll
    for (int k = 4; k <= 64; k <<= 1) {
        const bool up = (((lane * 4) & k) == 0);
        #pragma unroll
        for (int j = k >> 1; j >= 4; j >>= 1)
            shfl_stage(it, lane, j, up);
        ce(it[0], it[2], up); ce(it[1], it[3], up);   // j=2
        ce(it[0], it[1], up); ce(it[2], it[3], up);   // j=1
    }

    // k = 128: up depends on warp bit 0
    {
        const bool up = ((w & 1) == 0);
        #pragma unroll
        for (int j = 64; j >= 4; j >>= 1)
            shfl_stage(it, lane, j, up);
        ce(it[0], it[2], up); ce(it[1], it[3], up);
        ce(it[0], it[1], up); ce(it[2], it[3], up);
    }

    // k = 256: j=128 via smem, then intra-warp; up = (w < 2)
    {
        const bool up = (w < 2);
        __syncthreads();
        #pragma unroll
        for (int v = 0; v < 4; ++v) ssort[i0 + v] = it[v];
        __syncthreads();
        #pragma unroll
        for (int v = 0; v < 4; ++v) {
            unsigned long long o = ssort[(i0 + v) ^ 128];
            bool keepmin = ((((i0 + v) & 128) == 0) == up);
            if ((o < it[v]) == keepmin) it[v] = o;
        }
        #pragma unroll
        for (int j = 64; j >= 4; j >>= 1)
            shfl_stage(it, lane, j, up);
        ce(it[0], it[2], up); ce(it[1], it[3], up);
        ce(it[0], it[1], up); ce(it[2], it[3], up);
    }

    // k = 512: j=256,128 via smem, then intra-warp; up = true
    {
        #pragma unroll
        for (int j = 256; j >= 128; j >>= 1) {
            __syncthreads();
            #pragma unroll
            for (int v = 0; v < 4; ++v) ssort[i0 + v] = it[v];
            __syncthreads();
            #pragma unroll
            for (int v = 0; v < 4; ++v) {
                unsigned long long o = ssort[(i0 + v) ^ j];
                bool keepmin = (((i0 + v) & j) == 0);
                if ((o < it[v]) == keepmin) it[v] = o;
            }
        }
        #pragma unroll
        for (int j = 64; j >= 4; j >>= 1)
            shfl_stage(it, lane, j, true);
        ce(it[0], it[2], true); ce(it[1], it[3], true);
        ce(it[0], it[1], true); ce(it[2], it[3], true);
    }

    // ---- inverse permutation: sinv[src] = sorted position ----
    #pragma unroll
    for (int v = 0; v < 4; ++v)
        sinv[(int)(it[v] & 0x1FFu)] = (uint16_t)(i0 + v);
    __syncthreads();

    // ---- scatter: linear LDS.128, quad-contiguous 64B __stcs chunks ----
    float4* __restrict__ out4 = (float4*)(out + row * 8192);
    #pragma unroll
    for (int half = 0; half < 2; ++half) {
        int    dst[8];
        float4 v4[8];
        #pragma unroll
        for (int u = 0; u < 8; ++u) {
            int f  = (half * 8 + u) * 128 + t;
            dst[u] = sinv[f >> 2];            // quad-broadcast LDS
            v4[u]  = sdata[f];                // linear, conflict-free
        }
        #pragma unroll
        for (int u = 0; u < 8; ++u)
            __stcs(&out4[dst[u] * 4 + (t & 3)], v4[u]);   // full-sector 64B chunk
    }
}

extern "C" void kernel_launch(void* const* d_in, const int* in_sizes, int n_in,
                              void* d_out, int out_size)
{
    const float* z = (const float*)d_in[0];
    float* out     = (float*)d_out;
    const int D = 8192;                  // 512 packets * 16 floats
    int B = in_sizes[0] / D;             // 4096

    static int inited = 0;
    if (!inited) {
        cudaFuncSetAttribute(sort_latent_r14,
                             cudaFuncAttributeMaxDynamicSharedMemorySize,
                             SMEM_TOTAL);
        inited = 1;
    }
    sort_latent_r14<<<B, THREADS, SMEM_TOTAL>>>(z, out);
}